// round 6
// baseline (speedup 1.0000x reference)
#include <cuda_runtime.h>
#include <cstdint>

typedef unsigned long long ull;

__device__ __forceinline__ ull pack2(float x) {
    ull r; asm("mov.b64 %0, {%1, %1};" : "=l"(r) : "f"(x)); return r;
}
__device__ __forceinline__ void ffma2(ull &d, ull a, ull b) {
    asm("fma.rn.f32x2 %0, %1, %2, %0;" : "+l"(d) : "l"(a), "l"(b));
}
__device__ __forceinline__ void unpack2(ull v, float &lo, float &hi) {
    asm("mov.b64 {%0, %1}, %2;" : "=f"(lo), "=f"(hi) : "l"(v));
}
__device__ __forceinline__ uint32_t smem_u32(const void* p) {
    uint32_t a;
    asm("{ .reg .u64 t; cvta.to.shared.u64 t, %1; cvt.u32.u64 %0, t; }"
        : "=r"(a) : "l"(p));
    return a;
}
#define CP_ASYNC16(dst, src) \
    asm volatile("cp.async.cg.shared.global [%0], [%1], 16;" :: "r"(dst), "l"(src))
#define CP_COMMIT()  asm volatile("cp.async.commit_group;" ::: "memory")
#define CP_WAIT(N)   asm volatile("cp.async.wait_group %0;" :: "n"(N) : "memory")

// Per-node per-chunk row: [x0 16][x1 48][pad 4] = 68 floats (272B, 16B-aligned)
#define ROWF 68
#define BUFW (16 * ROWF)              // per-warp buffer: 16 nodes = 1088 floats
#define XRW  (2 * BUFW)               // double buffered = 2176 floats
#define WSH  8192                     // weights: 4 tensors x 2048 (scaled, h-major)
#define SMEM_FLOATS (WSH + 8 * XRW)   // 8192 + 17408 = 25600
#define SMEM_BYTES  (SMEM_FLOATS * 4) // 102400 (x2 CTA = 200 KB, fits)

// 2 threads per node: lane = h*16 + nl. Thread (nl,h) accumulates, for node nl,
// w-columns {2h, 2h+1} x all v x all groups = 32 ull accumulators.
// Weight smem layout (scaled by 0.01*C):
//   Wm[u*64 + h*32 + t*8 + v*2 + dw] = c_t * w_t[u, v, 2h+dw]
// so a thread's per-u weights are 32 contiguous floats = 8 LDS.128,
// 2 distinct addresses per instruction (one per half) = 1 wavefront each.

__device__ __forceinline__ void stage_chunk(
    uint32_t xr, const float* __restrict__ nfwarp, int c, int nl, int pc)
{
    const float* nsrc = nfwarp + (size_t)nl * 512;
    #pragma unroll
    for (int j = 0; j < 8; j++) {
        int p   = pc * 8 + j;
        int so  = (p < 4) ? (16*c + 4*p) : (128 + 48*c + 4*(p - 4));
        int doo = (p < 4) ? (4*p)        : (16 + 4*(p - 4));
        CP_ASYNC16(xr + (uint32_t)(nl * ROWF + doo) * 4u, nsrc + so);
    }
}

__global__ void __launch_bounds__(256, 2) fctp_main(
    const float* __restrict__ nf, const float* __restrict__ pf,
    const float* __restrict__ w000, const float* __restrict__ w011,
    const float* __restrict__ w101, const float* __restrict__ w110,
    float* __restrict__ out)
{
    extern __shared__ float S[];
    float* Wm = S;
    const int tid  = threadIdx.x;
    const int warp = tid >> 5, lane = tid & 31;
    const int nl = lane & 15, h = lane >> 4;

    // Stage weights, h-major per u
    {
        const float c000 = 3.125e-4f;                // 0.01/32
        const float c110 = 1.8042195912175807e-4f;   // 0.01/(32*sqrt(3))
        for (int i = tid; i < 2048; i += 256) {
            int u = i >> 4, j = i & 15, v = j >> 2, w = j & 3;
            int hh = w >> 1, dw = w & 1;
            int base = u*64 + hh*32 + v*2 + dw;
            Wm[base +  0] = c000 * w000[i];   // t=0
            Wm[base +  8] = c000 * w011[i];   // t=1
            Wm[base + 16] = c110 * w110[i];   // t=2
            Wm[base + 24] = c000 * w101[i];   // t=3
        }
    }
    __syncthreads();

    float* XR = S + WSH + warp * XRW;
    const uint32_t xr0 = smem_u32(XR);
    const uint32_t xr1 = xr0 + BUFW * 4u;
    const int node0 = blockIdx.x * 128 + warp * 16;   // warp's first node
    const float* nfwarp = nf + (size_t)node0 * 512;

    // Accumulators: [v] pairs of (w=2h, w=2h+1). 32 ull = 64 fp32.
    ull z000[4], z011[4], z110[3][4], z101[3][4];
    #pragma unroll
    for (int v = 0; v < 4; v++) {
        z000[v] = 0ull; z011[v] = 0ull;
        z110[0][v] = 0ull; z110[1][v] = 0ull; z110[2][v] = 0ull;
        z101[0][v] = 0ull; z101[1][v] = 0ull; z101[2][v] = 0ull;
    }

    const float* myrow0 = XR + nl * ROWF;
    const float* myrow1 = myrow0 + BUFW;

    stage_chunk(xr0, nfwarp, 0, nl, h);
    CP_COMMIT();

    for (int c = 0; c < 8; c++) {                 // 8 chunks of 16 u's
        if (c < 7) {
            stage_chunk((c & 1) ? xr0 : xr1, nfwarp, c + 1, nl, h);
            CP_COMMIT();
            CP_WAIT(1);
        } else {
            CP_WAIT(0);
        }
        __syncwarp();

        const float* myrow = (c & 1) ? myrow1 : myrow0;
        #pragma unroll
        for (int g = 0; g < 4; g++) {             // 4 u's per group
            float4 q0 = *reinterpret_cast<const float4*>(myrow + 4*g);
            float4 qa = *reinterpret_cast<const float4*>(myrow + 16 + 12*g);
            float4 qb = *reinterpret_cast<const float4*>(myrow + 16 + 12*g + 4);
            float4 qc = *reinterpret_cast<const float4*>(myrow + 16 + 12*g + 8);
            float x0s[4] = { q0.x, q0.y, q0.z, q0.w };
            float f1[12] = { qa.x, qa.y, qa.z, qa.w,
                             qb.x, qb.y, qb.z, qb.w,
                             qc.x, qc.y, qc.z, qc.w };
            #pragma unroll
            for (int j = 0; j < 4; j++) {
                const int u = 16*c + 4*g + j;
                const ulonglong2* wp =
                    reinterpret_cast<const ulonglong2*>(Wm + u*64 + h*32);
                ull xa  = pack2(x0s[j]);
                ull xb0 = pack2(f1[3*j + 0]);
                ull xb1 = pack2(f1[3*j + 1]);
                ull xb2 = pack2(f1[3*j + 2]);

                ulonglong2 t0a = wp[0], t0b = wp[1];      // w000: v0v1, v2v3
                ffma2(z000[0], xa, t0a.x); ffma2(z000[1], xa, t0a.y);
                ffma2(z000[2], xa, t0b.x); ffma2(z000[3], xa, t0b.y);

                ulonglong2 t1a = wp[2], t1b = wp[3];      // w011
                ffma2(z011[0], xa, t1a.x); ffma2(z011[1], xa, t1a.y);
                ffma2(z011[2], xa, t1b.x); ffma2(z011[3], xa, t1b.y);

                ulonglong2 t2a = wp[4], t2b = wp[5];      // w110 (x1 comps)
                ffma2(z110[0][0], xb0, t2a.x); ffma2(z110[0][1], xb0, t2a.y);
                ffma2(z110[0][2], xb0, t2b.x); ffma2(z110[0][3], xb0, t2b.y);
                ffma2(z110[1][0], xb1, t2a.x); ffma2(z110[1][1], xb1, t2a.y);
                ffma2(z110[1][2], xb1, t2b.x); ffma2(z110[1][3], xb1, t2b.y);
                ffma2(z110[2][0], xb2, t2a.x); ffma2(z110[2][1], xb2, t2a.y);
                ffma2(z110[2][2], xb2, t2b.x); ffma2(z110[2][3], xb2, t2b.y);

                ulonglong2 t3a = wp[6], t3b = wp[7];      // w101 (x1 comps)
                ffma2(z101[0][0], xb0, t3a.x); ffma2(z101[0][1], xb0, t3a.y);
                ffma2(z101[0][2], xb0, t3b.x); ffma2(z101[0][3], xb0, t3b.y);
                ffma2(z101[1][0], xb1, t3a.x); ffma2(z101[1][1], xb1, t3a.y);
                ffma2(z101[1][2], xb1, t3b.x); ffma2(z101[1][3], xb1, t3b.y);
                ffma2(z101[2][0], xb2, t3a.x); ffma2(z101[2][1], xb2, t3a.y);
                ffma2(z101[2][2], xb2, t3b.x); ffma2(z101[2][3], xb2, t3b.y);
            }
        }
        __syncwarp();   // buffer reused next chunk
    }

    // ---------------- epilogue (registers only) ----------------
    const int node = node0 + nl;

    float f000[4][2], f011[4][2], f110[3][4][2], f101[3][4][2];
    #pragma unroll
    for (int v = 0; v < 4; v++) {
        unpack2(z000[v], f000[v][0], f000[v][1]);
        unpack2(z011[v], f011[v][0], f011[v][1]);
        #pragma unroll
        for (int i = 0; i < 3; i++) {
            unpack2(z110[i][v], f110[i][v][0], f110[i][v][1]);
            unpack2(z101[i][v], f101[i][v][0], f101[i][v][1]);
        }
    }

    float y0v[4], y1v[4][3];
    {
        const float4* p4 = reinterpret_cast<const float4*>(pf + (size_t)node * 16);
        float4 t0 = p4[0], t1 = p4[1], t2 = p4[2], t3 = p4[3];
        y0v[0]=t0.x; y0v[1]=t0.y; y0v[2]=t0.z; y0v[3]=t0.w;
        y1v[0][0]=t1.x; y1v[0][1]=t1.y; y1v[0][2]=t1.z;
        y1v[1][0]=t1.w; y1v[1][1]=t2.x; y1v[1][2]=t2.y;
        y1v[2][0]=t2.z; y1v[2][1]=t2.w; y1v[3][0]=t3.x;
        y1v[3][1]=t3.y; y1v[3][2]=t3.z;
        // careful: y1[v][i] = pf[4 + 3v + i]; above maps t1.x=pf[4]...t3.z=pf[14]
        y1v[2][2]=t3.x;  // fix: pf[12]? recompute below
    }
    // Recompute y1v cleanly from scalar loads of pf (avoid mapping bugs):
    {
        const float* yp = pf + (size_t)node * 16;
        #pragma unroll
        for (int v = 0; v < 4; v++)
            #pragma unroll
            for (int i = 0; i < 3; i++)
                y1v[v][i] = yp[4 + 3*v + i];
    }

    float o0[2], o1[2][3];
    #pragma unroll
    for (int ww = 0; ww < 2; ww++) {
        float s = 0.f;
        #pragma unroll
        for (int v = 0; v < 4; v++) {
            s += f000[v][ww] * y0v[v];
            #pragma unroll
            for (int i = 0; i < 3; i++)
                s += f110[i][v][ww] * y1v[v][i];
        }
        o0[ww] = s;
        #pragma unroll
        for (int k = 0; k < 3; k++) {
            float t = 0.f;
            #pragma unroll
            for (int v = 0; v < 4; v++)
                t += f011[v][ww] * y1v[v][k] + f101[k][v][ww] * y0v[v];
            o1[ww][k] = t;
        }
    }
    if (h == 0) o0[0] = 0.0f;   // reference zeroes out[:,0]

    float* op = out + (size_t)node * 16;
    op[2*h    ] = o0[0];
    op[2*h + 1] = o0[1];
    float* o1p = op + 4 + 6*h;   // h=0 -> floats 4..9 (w=0,1); h=1 -> 10..15 (w=2,3)
    o1p[0] = o1[0][0]; o1p[1] = o1[0][1]; o1p[2] = o1[0][2];
    o1p[3] = o1[1][0]; o1p[4] = o1[1][1]; o1p[5] = o1[1][2];
}

// naive tail kernel (only runs if n % 128 != 0; negligible work)
__global__ void fctp_tail(
    const float* __restrict__ nf, const float* __restrict__ pf,
    const float* __restrict__ w000, const float* __restrict__ w011,
    const float* __restrict__ w101, const float* __restrict__ w110,
    float* __restrict__ out, int start, int n)
{
    int node = start + blockIdx.x * blockDim.x + threadIdx.x;
    if (node >= n) return;
    const float* x = nf + (size_t)node * 512;
    const float* y = pf + (size_t)node * 16;
    float y0v[4], y1v[4][3];
    for (int v0 = 0; v0 < 4; v0++) {
        y0v[v0] = y[v0];
        for (int i = 0; i < 3; i++) y1v[v0][i] = y[4 + 3*v0 + i];
    }
    float o0[4] = {0,0,0,0}, o1[4][3] = {};
    for (int u = 0; u < 128; u++) {
        float x0u = x[u];
        float x1u[3] = { x[128 + 3*u], x[128 + 3*u + 1], x[128 + 3*u + 2] };
        for (int v0 = 0; v0 < 4; v0++) {
            float s110 = x1u[0]*y1v[v0][0] + x1u[1]*y1v[v0][1] + x1u[2]*y1v[v0][2];
            float xy0 = x0u * y0v[v0];
            for (int w = 0; w < 4; w++) {
                int idx = u*16 + v0*4 + w;
                o0[w] += 3.125e-4f * xy0 * w000[idx]
                       + 1.8042195912175807e-4f * s110 * w110[idx];
                for (int k = 0; k < 3; k++)
                    o1[w][k] += 3.125e-4f * (x0u * y1v[v0][k] * w011[idx]
                                           + x1u[k] * y0v[v0] * w101[idx]);
            }
        }
    }
    o0[0] = 0.0f;
    float* op = out + (size_t)node * 16;
    for (int w = 0; w < 4; w++) op[w] = o0[w];
    for (int w = 0; w < 4; w++)
        for (int k = 0; k < 3; k++) op[4 + 3*w + k] = o1[w][k];
}

extern "C" void kernel_launch(void* const* d_in, const int* in_sizes, int n_in,
                              void* d_out, int out_size) {
    const float* nf   = (const float*)d_in[0];
    const float* pf   = (const float*)d_in[1];
    const float* w000 = (const float*)d_in[2];
    const float* w011 = (const float*)d_in[3];
    const float* w101 = (const float*)d_in[4];
    const float* w110 = (const float*)d_in[5];
    float* out = (float*)d_out;
    int n = in_sizes[0] / 512;
    int nb  = n >> 7;
    int rem = n & 127;
    cudaFuncSetAttribute(fctp_main, cudaFuncAttributeMaxDynamicSharedMemorySize, SMEM_BYTES);
    if (nb > 0)
        fctp_main<<<nb, 256, SMEM_BYTES>>>(nf, pf, w000, w011, w101, w110, out);
    if (rem > 0)
        fctp_tail<<<1, 128>>>(nf, pf, w000, w011, w101, w110, out, nb * 128, n);
}

// round 8
// speedup vs baseline: 1.2664x; 1.2664x over previous
#include <cuda_runtime.h>
#include <cstdint>

typedef unsigned long long ull;

__device__ __forceinline__ ull pack2(float x) {
    ull r; asm("mov.b64 %0, {%1, %1};" : "=l"(r) : "f"(x)); return r;
}
__device__ __forceinline__ void ffma2(ull &d, ull a, ull b) {
    asm("fma.rn.f32x2 %0, %1, %2, %0;" : "+l"(d) : "l"(a), "l"(b));
}
__device__ __forceinline__ void unpack2(ull v, float &lo, float &hi) {
    asm("mov.b64 {%0, %1}, %2;" : "=f"(lo), "=f"(hi) : "l"(v));
}
__device__ __forceinline__ uint32_t smem_u32(const void* p) {
    uint32_t a;
    asm("{ .reg .u64 t; cvta.to.shared.u64 t, %1; cvt.u32.u64 %0, t; }"
        : "=r"(a) : "l"(p));
    return a;
}
#define CP_ASYNC16(dst, src) \
    asm volatile("cp.async.cg.shared.global [%0], [%1], 16;" :: "r"(dst), "l"(src))
#define CP_COMMIT()  asm volatile("cp.async.commit_group;" ::: "memory")
#define CP_WAIT(N)   asm volatile("cp.async.wait_group %0;" :: "n"(N) : "memory")

// Chunk = 8 u's. Per-node per-chunk row: [x0 8][x1 24][pad 4] = 36 floats
// (144B: 16B-aligned rows; lane-stride 36 words -> conflict-free LDS.128 phases)
#define ROWF 36
#define BUFF (32 * ROWF)              // one buffer: 32 nodes = 1152 floats
#define NBUF 3
#define XRW  (NBUF * BUFF)            // 3456 floats per warp
#define WSH  8192                     // weights: 4 x 2048 floats (scaled)
#define SMEM_FLOATS (WSH + 4 * XRW)   // 8192 + 13824 = 22016
#define SMEM_BYTES  (SMEM_FLOATS * 4) // 88064 (x2 CTAs = 176 KB <= 228 KB)

// Stage chunk c (8 u's) for this warp's 32 nodes.
// lane = node_lo*8 + piece: each instruction covers 4 complete node rows
// (x0 32B + x1 96B contiguous pieces) -> few lines per instruction.
__device__ __forceinline__ void stage_chunk(
    uint32_t xr, const float* __restrict__ nfwarp, int c, int lane)
{
    const int node_lo = lane >> 3, piece = lane & 7;
    const int so  = (piece < 2) ? (8*c + 4*piece) : (128 + 24*c + 4*(piece - 2));
    const int doo = (piece < 2) ? (4*piece)       : (8 + 4*(piece - 2));
    #pragma unroll
    for (int i = 0; i < 8; i++) {
        int node = node_lo * 8 + i;
        CP_ASYNC16(xr + (uint32_t)(node * ROWF + doo) * 4u,
                   nfwarp + (size_t)node * 512 + so);
    }
}

__global__ void __launch_bounds__(128, 2) fctp_main(
    const float* __restrict__ nf, const float* __restrict__ pf,
    const float* __restrict__ w000, const float* __restrict__ w011,
    const float* __restrict__ w101, const float* __restrict__ w110,
    float* __restrict__ out)
{
    extern __shared__ float S[];
    float* Wm = S;
    const int tid  = threadIdx.x;
    const int warp = tid >> 5, lane = tid & 31;

    // Weights scaled by 0.01*C; per u: [w000 16][w011 16][w110 16][w101 16]
    {
        const float c000 = 3.125e-4f;                // 0.01/32
        const float c110 = 1.8042195912175807e-4f;   // 0.01/(32*sqrt(3))
        for (int i = tid; i < 2048; i += 128) {
            int u = i >> 4, j = i & 15;
            Wm[u*64 +      j] = c000 * w000[i];
            Wm[u*64 + 16 + j] = c000 * w011[i];
            Wm[u*64 + 32 + j] = c110 * w110[i];
            Wm[u*64 + 48 + j] = c000 * w101[i];
        }
    }
    __syncthreads();

    float* XR = S + WSH + warp * XRW;
    const uint32_t xrb = smem_u32(XR);
    const int nodeBase = blockIdx.x * 128 + warp * 32;
    const float* nfwarp = nf + (size_t)nodeBase * 512;

    // Accumulators: (v*4+w) col pairs. 64 ull = 128 fp32.
    ull z000[8], z011[8], z110[3][8], z101[3][8];
    #pragma unroll
    for (int p = 0; p < 8; p++) {
        z000[p] = 0ull; z011[p] = 0ull;
        z110[0][p] = 0ull; z110[1][p] = 0ull; z110[2][p] = 0ull;
        z101[0][p] = 0ull; z101[1][p] = 0ull; z101[2][p] = 0ull;
    }

    // depth-2 pipeline prologue
    stage_chunk(xrb,             nfwarp, 0, lane);  CP_COMMIT();
    stage_chunk(xrb + BUFF * 4u, nfwarp, 1, lane);  CP_COMMIT();

    for (int c = 0; c < 16; c++) {                    // 16 chunks of 8 u's
        if (c < 14) {
            stage_chunk(xrb + (uint32_t)(((c + 2) % NBUF) * BUFF) * 4u,
                        nfwarp, c + 2, lane);
            CP_COMMIT();
            CP_WAIT(2);                               // chunk c's group done
        } else if (c == 14) {
            CP_WAIT(1);
        } else {
            CP_WAIT(0);
        }
        __syncwarp();

        const float* myrow = XR + (c % NBUF) * BUFF + lane * ROWF;
        #pragma unroll
        for (int g = 0; g < 2; g++) {                 // 2 groups of 4 u's
            float4 q0 = *reinterpret_cast<const float4*>(myrow + 4*g);
            float4 qa = *reinterpret_cast<const float4*>(myrow + 8 + 12*g);
            float4 qb = *reinterpret_cast<const float4*>(myrow + 8 + 12*g + 4);
            float4 qc = *reinterpret_cast<const float4*>(myrow + 8 + 12*g + 8);
            float x0s[4] = { q0.x, q0.y, q0.z, q0.w };
            float f1[12] = { qa.x, qa.y, qa.z, qa.w,
                             qb.x, qb.y, qb.z, qb.w,
                             qc.x, qc.y, qc.z, qc.w };
            #pragma unroll
            for (int j = 0; j < 4; j++) {
                const int u = 8*c + 4*g + j;
                const ulonglong2* wp =
                    reinterpret_cast<const ulonglong2*>(Wm + u * 64);
                ull xa  = pack2(x0s[j]);
                ull xb0 = pack2(f1[3*j + 0]);
                ull xb1 = pack2(f1[3*j + 1]);
                ull xb2 = pack2(f1[3*j + 2]);
                #pragma unroll
                for (int p = 0; p < 4; p++) {         // w000 (x0)
                    ulonglong2 w = wp[p];
                    ffma2(z000[2*p],   xa, w.x);
                    ffma2(z000[2*p+1], xa, w.y);
                }
                #pragma unroll
                for (int p = 0; p < 4; p++) {         // w011 (x0)
                    ulonglong2 w = wp[4 + p];
                    ffma2(z011[2*p],   xa, w.x);
                    ffma2(z011[2*p+1], xa, w.y);
                }
                #pragma unroll
                for (int p = 0; p < 4; p++) {         // w110 (x1[.,i])
                    ulonglong2 w = wp[8 + p];
                    ffma2(z110[0][2*p],   xb0, w.x);
                    ffma2(z110[0][2*p+1], xb0, w.y);
                    ffma2(z110[1][2*p],   xb1, w.x);
                    ffma2(z110[1][2*p+1], xb1, w.y);
                    ffma2(z110[2][2*p],   xb2, w.x);
                    ffma2(z110[2][2*p+1], xb2, w.y);
                }
                #pragma unroll
                for (int p = 0; p < 4; p++) {         // w101 (x1[.,k])
                    ulonglong2 w = wp[12 + p];
                    ffma2(z101[0][2*p],   xb0, w.x);
                    ffma2(z101[0][2*p+1], xb0, w.y);
                    ffma2(z101[1][2*p],   xb1, w.x);
                    ffma2(z101[1][2*p+1], xb1, w.y);
                    ffma2(z101[2][2*p],   xb2, w.x);
                    ffma2(z101[2][2*p+1], xb2, w.y);
                }
            }
        }
        __syncwarp();   // buffer (c%3) may be restaged at iteration c+1
    }

    // ---------------- epilogue (registers only) ----------------
    const int node = nodeBase + lane;

    float f000[16], f011[16], f110[3][16], f101[3][16];
    #pragma unroll
    for (int p = 0; p < 8; p++) {
        unpack2(z000[p], f000[2*p], f000[2*p+1]);
        unpack2(z011[p], f011[2*p], f011[2*p+1]);
        #pragma unroll
        for (int i = 0; i < 3; i++) {
            unpack2(z110[i][p], f110[i][2*p], f110[i][2*p+1]);
            unpack2(z101[i][p], f101[i][2*p], f101[i][2*p+1]);
        }
    }

    float y[16];
    {
        const float4* p4 = reinterpret_cast<const float4*>(pf + (size_t)node * 16);
        #pragma unroll
        for (int q = 0; q < 4; q++) {
            float4 t = p4[q];
            y[4*q+0] = t.x; y[4*q+1] = t.y; y[4*q+2] = t.z; y[4*q+3] = t.w;
        }
    }

    float o0[4], o1[4][3];
    #pragma unroll
    for (int w = 0; w < 4; w++) {
        float s = 0.f, t = 0.f;
        #pragma unroll
        for (int v = 0; v < 4; v++) {
            s += f000[v*4 + w] * y[v];
            #pragma unroll
            for (int i = 0; i < 3; i++)
                t += f110[i][v*4 + w] * y[4 + 3*v + i];
        }
        o0[w] = s + t;
    }
    #pragma unroll
    for (int w = 0; w < 4; w++) {
        #pragma unroll
        for (int k = 0; k < 3; k++) {
            float s = 0.f, t = 0.f;
            #pragma unroll
            for (int v = 0; v < 4; v++) {
                s += f011[v*4 + w]    * y[4 + 3*v + k];
                t += f101[k][v*4 + w] * y[v];
            }
            o1[w][k] = s + t;
        }
    }
    o0[0] = 0.0f;   // reference zeroes out[:,0]

    float4* o4 = reinterpret_cast<float4*>(out + (size_t)node * 16);
    o4[0] = make_float4(o0[0],    o0[1],    o0[2],    o0[3]);
    o4[1] = make_float4(o1[0][0], o1[0][1], o1[0][2], o1[1][0]);
    o4[2] = make_float4(o1[1][1], o1[1][2], o1[2][0], o1[2][1]);
    o4[3] = make_float4(o1[2][2], o1[3][0], o1[3][1], o1[3][2]);
}

// naive tail kernel (only runs if n % 128 != 0; negligible work)
__global__ void fctp_tail(
    const float* __restrict__ nf, const float* __restrict__ pf,
    const float* __restrict__ w000, const float* __restrict__ w011,
    const float* __restrict__ w101, const float* __restrict__ w110,
    float* __restrict__ out, int start, int n)
{
    int node = start + blockIdx.x * blockDim.x + threadIdx.x;
    if (node >= n) return;
    const float* x = nf + (size_t)node * 512;
    const float* y = pf + (size_t)node * 16;
    float y0v[4], y1v[4][3];
    for (int v0 = 0; v0 < 4; v0++) {
        y0v[v0] = y[v0];
        for (int i = 0; i < 3; i++) y1v[v0][i] = y[4 + 3*v0 + i];
    }
    float o0[4] = {0,0,0,0}, o1[4][3] = {};
    for (int u = 0; u < 128; u++) {
        float x0u = x[u];
        float x1u[3] = { x[128 + 3*u], x[128 + 3*u + 1], x[128 + 3*u + 2] };
        for (int v0 = 0; v0 < 4; v0++) {
            float s110 = x1u[0]*y1v[v0][0] + x1u[1]*y1v[v0][1] + x1u[2]*y1v[v0][2];
            float xy0 = x0u * y0v[v0];
            for (int w = 0; w < 4; w++) {
                int idx = u*16 + v0*4 + w;
                o0[w] += 3.125e-4f * xy0 * w000[idx]
                       + 1.8042195912175807e-4f * s110 * w110[idx];
                for (int k = 0; k < 3; k++)
                    o1[w][k] += 3.125e-4f * (x0u * y1v[v0][k] * w011[idx]
                                           + x1u[k] * y0v[v0] * w101[idx]);
            }
        }
    }
    o0[0] = 0.0f;
    float* op = out + (size_t)node * 16;
    for (int w = 0; w < 4; w++) op[w] = o0[w];
    for (int w = 0; w < 4; w++)
        for (int k = 0; k < 3; k++) op[4 + 3*w + k] = o1[w][k];
}

extern "C" void kernel_launch(void* const* d_in, const int* in_sizes, int n_in,
                              void* d_out, int out_size) {
    const float* nf   = (const float*)d_in[0];
    const float* pf   = (const float*)d_in[1];
    const float* w000 = (const float*)d_in[2];
    const float* w011 = (const float*)d_in[3];
    const float* w101 = (const float*)d_in[4];
    const float* w110 = (const float*)d_in[5];
    float* out = (float*)d_out;
    int n = in_sizes[0] / 512;
    int nb  = n >> 7;
    int rem = n & 127;
    cudaFuncSetAttribute(fctp_main, cudaFuncAttributeMaxDynamicSharedMemorySize, SMEM_BYTES);
    if (nb > 0)
        fctp_main<<<nb, 128, SMEM_BYTES>>>(nf, pf, w000, w011, w101, w110, out);
    if (rem > 0)
        fctp_tail<<<1, 128>>>(nf, pf, w000, w011, w101, w110, out, nb * 128, n);
}